// round 5
// baseline (speedup 1.0000x reference)
#include <cuda_runtime.h>
#include <cuda_bf16.h>
#include <cstdint>

// ---------------- problem geometry (static) ----------------
#define CC   96
#define HDIM 64
#define WDIM 64
#define HW   4096
#define DHW  131072
#define CDHW (CC*DHW)
#define D2   16
#define H2   32
#define W2   32
#define OSP  16384
#define KDIM 768
#define NDIM 192
#define NCHK 4                   // K chunks of 192 (one octant-pair each)
#define NCTA 512                 // 32768 rows / 64

// ---------------- smem layout (bytes) ----------------
#define ASTR 400                 // 192 bf16 + 8 pad ; 400/16=25 (odd) -> ldmatrix conflict-free
#define SZ_AH (64*ASTR)          // 25600
#define OFF_AL SZ_AH             // lo plane
#define OFF_PS   (2*SZ_AH)       // 51200 : ps[4*64]*2
#define OFF_RSTD (OFF_PS+2048)   // 53248 : rstd[64]
#define OFF_MRS  (OFF_RSTD+256)  // 53504 : mu*rstd[64]
#define SMEM_TOTAL (OFF_MRS+256) // 53760  -> 2 CTAs/SM
#define CSTR 65                  // epilogue staging stride (floats); 192*65*4=49920 < 51200

// ---------------- prep outputs ----------------
// B fragments: [kt 0..47][ntile 0..23][lane 0..31] = {bh0,bh1,bl0,bl1}
__device__ __align__(16) uint4 g_Bf[48*24*32];
__device__ float g_gW[NDIM];     // gamma @ W
__device__ float g_bW[NDIM];     // beta  @ W

// ---------------- helpers ----------------
__device__ __forceinline__ uint32_t smem_u32(const void* p) {
    uint32_t a;
    asm("{ .reg .u64 t; cvta.to.shared.u64 t, %1; cvt.u32.u64 %0, t; }" : "=r"(a) : "l"(p));
    return a;
}
__device__ __forceinline__ void ldsm4(uint32_t* r, uint32_t addr) {
    asm volatile("ldmatrix.sync.aligned.m8n8.x4.shared.b16 {%0,%1,%2,%3}, [%4];"
                 : "=r"(r[0]), "=r"(r[1]), "=r"(r[2]), "=r"(r[3]) : "r"(addr));
}
__device__ __forceinline__ void mma_bf16(float* c, const uint32_t* a, uint32_t b0, uint32_t b1) {
    asm volatile("mma.sync.aligned.m16n8k16.row.col.f32.bf16.bf16.f32 "
                 "{%0,%1,%2,%3}, {%4,%5,%6,%7}, {%8,%9}, {%0,%1,%2,%3};"
                 : "+f"(c[0]), "+f"(c[1]), "+f"(c[2]), "+f"(c[3])
                 : "r"(a[0]), "r"(a[1]), "r"(a[2]), "r"(a[3]), "r"(b0), "r"(b1));
}
// split (a,b) -> packed bf16 hi pair + lo pair
__device__ __forceinline__ void split2(float a, float b, uint32_t& hi, uint32_t& lo) {
    __nv_bfloat162 h = __floats2bfloat162_rn(a, b);
    uint32_t hu = *(uint32_t*)&h;
    float ha = __uint_as_float(hu << 16);
    float hb = __uint_as_float(hu & 0xffff0000u);
    __nv_bfloat162 l = __floats2bfloat162_rn(a - ha, b - hb);
    hi = hu; lo = *(uint32_t*)&l;
}

// ---------------- prep 1: gW / bW vectors (coalesced) ----------------
__global__ void prep_vec(const float* __restrict__ gamma,
                         const float* __restrict__ beta,
                         const float* __restrict__ w) {
    __shared__ float ps[512];
    const int tid = threadIdx.x;        // 256
    const int tn = tid & 31;
    const int kg = tid >> 5;            // 0..7
    const int n = blockIdx.x * 32 + tn;
    float sb = 0.f, sg = 0.f;
    for (int k = kg; k < KDIM; k += 8) {
        float wv = w[k * NDIM + n];     // 32 consecutive n -> coalesced
        sb += beta[k]  * wv;
        sg += gamma[k] * wv;
    }
    ps[kg * 32 + tn] = sb;
    ps[256 + kg * 32 + tn] = sg;
    __syncthreads();
    if (tid < 32) {
        float SB = 0.f, SG = 0.f;
        #pragma unroll
        for (int j = 0; j < 8; j++) { SB += ps[j * 32 + tid]; SG += ps[256 + j * 32 + tid]; }
        g_bW[blockIdx.x * 32 + tid] = SB;
        g_gW[blockIdx.x * 32 + tid] = SG;
    }
}

// ---------------- prep 2: B mma-fragments (hi/lo), W' = diag(gamma)*W ----------------
__global__ void prep_frag(const float* __restrict__ gamma,
                          const float* __restrict__ w) {
    const int idx = blockIdx.x * 128 + threadIdx.x;   // 0..36863
    const int kt   = idx / 768;
    const int rem  = idx - kt * 768;
    const int nt   = rem >> 5;
    const int lane = rem & 31;
    const int n  = nt * 8 + (lane >> 2);
    const int k0 = kt * 16 + (lane & 3) * 2;

    float w00 = gamma[k0]     * w[(k0)     * NDIM + n];
    float w01 = gamma[k0 + 1] * w[(k0 + 1) * NDIM + n];
    float w10 = gamma[k0 + 8] * w[(k0 + 8) * NDIM + n];
    float w11 = gamma[k0 + 9] * w[(k0 + 9) * NDIM + n];

    uint32_t bh0, bl0, bh1, bl1;
    split2(w00, w01, bh0, bl0);
    split2(w10, w11, bh1, bl1);
    g_Bf[idx] = make_uint4(bh0, bh1, bl0, bl1);
}

// ---------------- fused single-pass gather + raw-GEMM + LN-affine epilogue ----------------
// grid 512 CTAs x 256 threads, 2 CTAs/SM; CTA computes rows [bid*64,+64) x 192 cols.
__global__ __launch_bounds__(256, 2)
void pm_kernel(const float* __restrict__ x, float* __restrict__ out) {
    extern __shared__ char smem[];
    const uint32_t sbase = smem_u32(smem);
    const int tid  = threadIdx.x;
    const int bid  = blockIdx.x;
    const int lane = tid & 31;
    const int wid  = tid >> 5;
    const int r    = tid & 63;    // A row this thread fills
    const int q    = tid >> 6;    // c-quarter within chunk (0..3)

    const int grp = bid * 2 + (r >> 5);
    const int h2i = grp & 31, d2i = (grp >> 5) & 15, bi = grp >> 9;
    const float* xr = x + (size_t)bi * CDHW + (2 * d2i) * HW + (2 * h2i) * WDIM + 2 * (r & 31);

    // mma geometry: 2(m) x 4(n) warps; warp tile 32 x 48
    const int wm = wid >> 2;
    const int wn = wid & 3;
    const uint32_t aoff = (uint32_t)(wm * 32 + (lane & 15)) * ASTR + (lane >> 4) * 16;

    float acc[2][6][4];
    #pragma unroll
    for (int mt = 0; mt < 2; mt++)
        #pragma unroll
        for (int nt = 0; nt < 6; nt++)
            #pragma unroll
            for (int e = 0; e < 4; e++) acc[mt][nt][e] = 0.f;

    float s = 0.f, s2 = 0.f;

    // ---- fill chunk ch (octant pair): raw y -> bf16 hi/lo in smem + stats ----
    auto fill = [&](int ch) {
        char* dst = smem + (uint32_t)r * ASTR;
        const float* xc = xr + (ch >> 1) * HW + (ch & 1) * WDIM;
        int c = q * 24;
        #pragma unroll
        for (int t = 0; t < 12; t++, c += 2) {
            float2 va = *(const float2*)(xc + (size_t)c * DHW);
            float2 vb = *(const float2*)(xc + (size_t)(c + 1) * DHW);
            s  += (va.x + va.y) + (vb.x + vb.y);
            s2 += va.x * va.x + va.y * va.y + vb.x * vb.x + vb.y * vb.y;
            uint32_t h0, l0, h1, l1;
            split2(va.x, vb.x, h0, l0);   // kl = c, c+1   (w=0 octant)
            split2(va.y, vb.y, h1, l1);   // kl = 96+c,+1  (w=1 octant)
            *(uint32_t*)(dst + 2 * c)                = h0;
            *(uint32_t*)(dst + 192 + 2 * c)          = h1;
            *(uint32_t*)(dst + OFF_AL + 2 * c)       = l0;
            *(uint32_t*)(dst + OFF_AL + 192 + 2 * c) = l1;
        }
    };

    // ---- mma over one chunk (12 k-steps, 3 split terms, B via LDG fragments) ----
    auto mmachunk = [&](int ch) {
        const uint4* bp = g_Bf + ((size_t)(ch * 12) * 24 + wn * 6) * 32 + lane;
        #pragma unroll
        for (int ks = 0; ks < 12; ks++) {
            uint32_t B[6][4];
            #pragma unroll
            for (int nt = 0; nt < 6; nt++) {
                uint4 v = __ldg(bp + (size_t)ks * 24 * 32 + nt * 32);
                B[nt][0] = v.x; B[nt][1] = v.y; B[nt][2] = v.z; B[nt][3] = v.w;
            }
            uint32_t af[2][4], al[2][4];
            #pragma unroll
            for (int mt = 0; mt < 2; mt++)
                ldsm4(af[mt], sbase + aoff + mt * (16 * ASTR) + ks * 32);
            #pragma unroll
            for (int mt = 0; mt < 2; mt++)
                ldsm4(al[mt], sbase + OFF_AL + aoff + mt * (16 * ASTR) + ks * 32);
            #pragma unroll
            for (int mt = 0; mt < 2; mt++)
                #pragma unroll
                for (int nt = 0; nt < 6; nt++)
                    mma_bf16(acc[mt][nt], af[mt], B[nt][0], B[nt][1]);
            #pragma unroll
            for (int mt = 0; mt < 2; mt++)
                #pragma unroll
                for (int nt = 0; nt < 6; nt++)
                    mma_bf16(acc[mt][nt], al[mt], B[nt][0], B[nt][1]);
            #pragma unroll
            for (int mt = 0; mt < 2; mt++)
                #pragma unroll
                for (int nt = 0; nt < 6; nt++)
                    mma_bf16(acc[mt][nt], af[mt], B[nt][2], B[nt][3]);
        }
    };

    #pragma unroll 1
    for (int ch = 0; ch < NCHK; ch++) {
        fill(ch);
        __syncthreads();
        mmachunk(ch);
        __syncthreads();
    }

    // ---- LN stats reduction ----
    float* ps = (float*)(smem + OFF_PS);
    ps[tid] = s; ps[256 + tid] = s2;
    __syncthreads();
    float* rstd_s = (float*)(smem + OFF_RSTD);
    float* mrs_s  = (float*)(smem + OFF_MRS);
    if (tid < 64) {
        float S = 0.f, S2 = 0.f;
        #pragma unroll
        for (int j = 0; j < 4; j++) { S += ps[j * 64 + tid]; S2 += ps[256 + j * 64 + tid]; }
        float mu  = S * (1.f / 768.f);
        float var = S2 * (1.f / 768.f) - mu * mu;
        float rstd = rsqrtf(var + 1e-5f);
        rstd_s[tid] = rstd;
        mrs_s[tid]  = mu * rstd;
    }
    __syncthreads();

    // ---- epilogue: stage C transposed in smem (A region), coalesced affine store ----
    float* Csm = (float*)smem;
    #pragma unroll
    for (int mt = 0; mt < 2; mt++) {
        int row = wm * 32 + mt * 16 + (lane >> 2);
        #pragma unroll
        for (int nt = 0; nt < 6; nt++) {
            int n = wn * 48 + nt * 8 + 2 * (lane & 3);
            Csm[n * CSTR + row]           = acc[mt][nt][0];
            Csm[(n + 1) * CSTR + row]     = acc[mt][nt][1];
            Csm[n * CSTR + row + 8]       = acc[mt][nt][2];
            Csm[(n + 1) * CSTR + row + 8] = acc[mt][nt][3];
        }
    }
    __syncthreads();
    #pragma unroll 8
    for (int i = 0; i < 48; i++) {
        int idx = tid + 256 * i;
        int n = idx >> 6, row = idx & 63;
        float val = rstd_s[row] * Csm[n * CSTR + row] - mrs_s[row] * g_gW[n] + g_bW[n];
        int grp2 = bid * 2 + (row >> 5);
        int h2o = grp2 & 31, d2o = (grp2 >> 5) & 15, bo = grp2 >> 9;
        out[(size_t)bo * NDIM * OSP + (size_t)n * OSP + d2o * (H2 * W2) + h2o * W2 + (row & 31)] = val;
    }
}

// ---------------- launch ----------------
extern "C" void kernel_launch(void* const* d_in, const int* in_sizes, int n_in,
                              void* d_out, int out_size) {
    const float* x     = (const float*)d_in[0];
    const float* gamma = (const float*)d_in[1];
    const float* beta  = (const float*)d_in[2];
    const float* w     = (const float*)d_in[3];
    float* out = (float*)d_out;

    cudaFuncSetAttribute(pm_kernel, cudaFuncAttributeMaxDynamicSharedMemorySize, SMEM_TOTAL);

    prep_vec<<<6, 256>>>(gamma, beta, w);
    prep_frag<<<288, 128>>>(gamma, w);
    pm_kernel<<<NCTA, 256, SMEM_TOTAL>>>(x, out);
}

// round 6
// speedup vs baseline: 1.3094x; 1.3094x over previous
#include <cuda_runtime.h>
#include <cuda_bf16.h>
#include <cstdint>

// ---------------- problem geometry (static) ----------------
#define CC   96
#define HDIM 64
#define WDIM 64
#define HW   4096
#define DHW  131072
#define CDHW (CC*DHW)
#define D2   16
#define H2   32
#define W2   32
#define OSP  16384
#define KDIM 768
#define NDIM 192
#define NCHK 4                   // K chunks of 192 (one octant-pair each)
#define NCTA 512                 // 32768 rows / 64

// ---------------- smem layout (bytes) ----------------
#define ASTR 400                 // 192 bf16 + 8 pad ; conflict-free for ldmatrix
#define SZ_AH (64*ASTR)          // 25600
#define OFF_AL SZ_AH             // lo plane
#define OFF_PS   (2*SZ_AH)       // 51200 : ps[256]*2
#define OFF_RSTD (OFF_PS+2048)   // 53248 : rstd[64]
#define OFF_MRS  (OFF_RSTD+256)  // 53504 : mu*rstd[64]
#define SMEM_TOTAL (OFF_MRS+256) // 53760  -> 2 CTAs/SM
#define CSTR 65                  // epilogue staging stride (floats); 192*65*4=49920 < 51200

// ---------------- prep outputs ----------------
// B fragments: [kt 0..47][ntile 0..23][lane 0..31] = {bh0,bh1,bl0,bl1}
__device__ __align__(16) uint4 g_Bf[48*24*32];
__device__ float g_gW[NDIM];     // gamma @ W
__device__ float g_bW[NDIM];     // beta  @ W

// ---------------- helpers ----------------
__device__ __forceinline__ uint32_t smem_u32(const void* p) {
    uint32_t a;
    asm("{ .reg .u64 t; cvta.to.shared.u64 t, %1; cvt.u32.u64 %0, t; }" : "=r"(a) : "l"(p));
    return a;
}
__device__ __forceinline__ void ldsm4(uint32_t* r, uint32_t addr) {
    asm volatile("ldmatrix.sync.aligned.m8n8.x4.shared.b16 {%0,%1,%2,%3}, [%4];"
                 : "=r"(r[0]), "=r"(r[1]), "=r"(r[2]), "=r"(r[3]) : "r"(addr));
}
__device__ __forceinline__ void mma_bf16(float* c, const uint32_t* a, uint32_t b0, uint32_t b1) {
    asm volatile("mma.sync.aligned.m16n8k16.row.col.f32.bf16.bf16.f32 "
                 "{%0,%1,%2,%3}, {%4,%5,%6,%7}, {%8,%9}, {%0,%1,%2,%3};"
                 : "+f"(c[0]), "+f"(c[1]), "+f"(c[2]), "+f"(c[3])
                 : "r"(a[0]), "r"(a[1]), "r"(a[2]), "r"(a[3]), "r"(b0), "r"(b1));
}
// split (a,b) -> packed bf16 hi pair + lo pair
__device__ __forceinline__ void split2(float a, float b, uint32_t& hi, uint32_t& lo) {
    __nv_bfloat162 h = __floats2bfloat162_rn(a, b);
    uint32_t hu = *(uint32_t*)&h;
    float ha = __uint_as_float(hu << 16);
    float hb = __uint_as_float(hu & 0xffff0000u);
    __nv_bfloat162 l = __floats2bfloat162_rn(a - ha, b - hb);
    hi = hu; lo = *(uint32_t*)&l;
}

// ---------------- prep 0: zero the accumulated vectors ----------------
__global__ void zero_vec() {
    int t = threadIdx.x;
    if (t < NDIM) { g_gW[t] = 0.f; g_bW[t] = 0.f; }
}

// ---------------- prep 1: gW / bW via row-coalesced partial sums + atomics ----------------
__global__ void prep_vec(const float* __restrict__ gamma,
                         const float* __restrict__ beta,
                         const float* __restrict__ w) {
    const int n  = threadIdx.x;          // 192
    const int k0 = blockIdx.x * 24;      // 32 blocks x 24 k-rows
    float sb = 0.f, sg = 0.f;
    #pragma unroll 4
    for (int k = k0; k < k0 + 24; k++) {
        float wv = __ldg(&w[k * NDIM + n]);   // 192 consecutive floats -> coalesced
        sb += __ldg(&beta[k])  * wv;
        sg += __ldg(&gamma[k]) * wv;
    }
    atomicAdd(&g_bW[n], sb);
    atomicAdd(&g_gW[n], sg);
}

// ---------------- prep 2: B mma-fragments (hi/lo), W' = diag(gamma)*W ----------------
__global__ void prep_frag(const float* __restrict__ gamma,
                          const float* __restrict__ w) {
    const int idx = blockIdx.x * 128 + threadIdx.x;   // 0..36863
    const int kt   = idx / 768;
    const int rem  = idx - kt * 768;
    const int nt   = rem >> 5;
    const int lane = rem & 31;
    const int n  = nt * 8 + (lane >> 2);
    const int k0 = kt * 16 + (lane & 3) * 2;

    float w00 = gamma[k0]     * w[(k0)     * NDIM + n];
    float w01 = gamma[k0 + 1] * w[(k0 + 1) * NDIM + n];
    float w10 = gamma[k0 + 8] * w[(k0 + 8) * NDIM + n];
    float w11 = gamma[k0 + 9] * w[(k0 + 9) * NDIM + n];

    uint32_t bh0, bl0, bh1, bl1;
    split2(w00, w01, bh0, bl0);
    split2(w10, w11, bh1, bl1);
    g_Bf[idx] = make_uint4(bh0, bh1, bl0, bl1);
}

// ---------------- fused single-pass gather + raw-GEMM + LN-affine epilogue ----------------
// grid 512 CTAs x 256 threads, 2 CTAs/SM; CTA computes rows [bid*64,+64) x 192 cols.
// Warp layout 1(m) x 8(n): warp tile 64 x 24 -> no B duplication across warps.
__global__ __launch_bounds__(256, 2)
void pm_kernel(const float* __restrict__ x, float* __restrict__ out) {
    extern __shared__ char smem[];
    const uint32_t sbase = smem_u32(smem);
    const int tid  = threadIdx.x;
    const int bid  = blockIdx.x;
    const int lane = tid & 31;
    const int wid  = tid >> 5;
    const int r    = tid & 63;    // A row this thread fills
    const int q    = tid >> 6;    // c-quarter within chunk (0..3)

    const int grp = bid * 2 + (r >> 5);
    const int h2i = grp & 31, d2i = (grp >> 5) & 15, bi = grp >> 9;
    const float* xr = x + (size_t)bi * CDHW + (2 * d2i) * HW + (2 * h2i) * WDIM + 2 * (r & 31);

    const uint32_t aoff = (uint32_t)(lane & 15) * ASTR + (lane >> 4) * 16;

    float acc[4][3][4];
    #pragma unroll
    for (int mt = 0; mt < 4; mt++)
        #pragma unroll
        for (int nt = 0; nt < 3; nt++)
            #pragma unroll
            for (int e = 0; e < 4; e++) acc[mt][nt][e] = 0.f;

    float s = 0.f, s2 = 0.f;

    // ---- fill chunk ch (octant pair): raw y -> bf16 hi/lo in smem + stats ----
    auto fill = [&](int ch) {
        char* dst = smem + (uint32_t)r * ASTR;
        const float* xc = xr + (ch >> 1) * HW + (ch & 1) * WDIM;
        int c = q * 24;
        #pragma unroll
        for (int t = 0; t < 12; t++, c += 2) {
            float2 va = *(const float2*)(xc + (size_t)c * DHW);
            float2 vb = *(const float2*)(xc + (size_t)(c + 1) * DHW);
            s  += (va.x + va.y) + (vb.x + vb.y);
            s2 += va.x * va.x + va.y * va.y + vb.x * vb.x + vb.y * vb.y;
            uint32_t h0, l0, h1, l1;
            split2(va.x, vb.x, h0, l0);   // kl = c, c+1   (w=0 octant)
            split2(va.y, vb.y, h1, l1);   // kl = 96+c,+1  (w=1 octant)
            *(uint32_t*)(dst + 2 * c)                = h0;
            *(uint32_t*)(dst + 192 + 2 * c)          = h1;
            *(uint32_t*)(dst + OFF_AL + 2 * c)       = l0;
            *(uint32_t*)(dst + OFF_AL + 192 + 2 * c) = l1;
        }
    };

    // ---- mma over one chunk (12 k-steps, 3 split terms, B via LDG fragments) ----
    auto mmachunk = [&](int ch) {
        const uint4* bp = g_Bf + ((size_t)(ch * 12) * 24 + wid * 3) * 32 + lane;
        uint32_t bb[2][3][4];
        #pragma unroll
        for (int nt = 0; nt < 3; nt++) {
            uint4 v = __ldg(bp + nt * 32);
            bb[0][nt][0] = v.x; bb[0][nt][1] = v.y; bb[0][nt][2] = v.z; bb[0][nt][3] = v.w;
        }
        #pragma unroll
        for (int ks = 0; ks < 12; ks++) {
            if (ks < 11) {
                const uint4* bp2 = bp + (size_t)(ks + 1) * 24 * 32;
                #pragma unroll
                for (int nt = 0; nt < 3; nt++) {
                    uint4 v = __ldg(bp2 + nt * 32);
                    bb[(ks + 1) & 1][nt][0] = v.x; bb[(ks + 1) & 1][nt][1] = v.y;
                    bb[(ks + 1) & 1][nt][2] = v.z; bb[(ks + 1) & 1][nt][3] = v.w;
                }
            }
            uint32_t af[4][4], al[4][4];
            #pragma unroll
            for (int mt = 0; mt < 4; mt++)
                ldsm4(af[mt], sbase + aoff + mt * (16 * ASTR) + ks * 32);
            #pragma unroll
            for (int mt = 0; mt < 4; mt++)
                ldsm4(al[mt], sbase + OFF_AL + aoff + mt * (16 * ASTR) + ks * 32);
            uint32_t (*B)[4] = bb[ks & 1];
            #pragma unroll
            for (int mt = 0; mt < 4; mt++)
                #pragma unroll
                for (int nt = 0; nt < 3; nt++)
                    mma_bf16(acc[mt][nt], af[mt], B[nt][0], B[nt][1]);
            #pragma unroll
            for (int mt = 0; mt < 4; mt++)
                #pragma unroll
                for (int nt = 0; nt < 3; nt++)
                    mma_bf16(acc[mt][nt], al[mt], B[nt][0], B[nt][1]);
            #pragma unroll
            for (int mt = 0; mt < 4; mt++)
                #pragma unroll
                for (int nt = 0; nt < 3; nt++)
                    mma_bf16(acc[mt][nt], af[mt], B[nt][2], B[nt][3]);
        }
    };

    #pragma unroll 1
    for (int ch = 0; ch < NCHK; ch++) {
        fill(ch);
        __syncthreads();
        mmachunk(ch);
        __syncthreads();
    }

    // ---- LN stats reduction ----
    float* ps = (float*)(smem + OFF_PS);
    ps[tid] = s; ps[256 + tid] = s2;
    __syncthreads();
    float* rstd_s = (float*)(smem + OFF_RSTD);
    float* mrs_s  = (float*)(smem + OFF_MRS);
    if (tid < 64) {
        float S = 0.f, S2 = 0.f;
        #pragma unroll
        for (int j = 0; j < 4; j++) { S += ps[j * 64 + tid]; S2 += ps[256 + j * 64 + tid]; }
        float mu  = S * (1.f / 768.f);
        float var = S2 * (1.f / 768.f) - mu * mu;
        float rstd = rsqrtf(var + 1e-5f);
        rstd_s[tid] = rstd;
        mrs_s[tid]  = mu * rstd;
    }
    __syncthreads();

    // ---- epilogue: stage C transposed in smem (A region), coalesced affine store ----
    float* Csm = (float*)smem;
    #pragma unroll
    for (int mt = 0; mt < 4; mt++) {
        int row = mt * 16 + (lane >> 2);
        #pragma unroll
        for (int nt = 0; nt < 3; nt++) {
            int n = wid * 24 + nt * 8 + 2 * (lane & 3);
            Csm[n * CSTR + row]           = acc[mt][nt][0];
            Csm[(n + 1) * CSTR + row]     = acc[mt][nt][1];
            Csm[n * CSTR + row + 8]       = acc[mt][nt][2];
            Csm[(n + 1) * CSTR + row + 8] = acc[mt][nt][3];
        }
    }
    __syncthreads();
    #pragma unroll 8
    for (int i = 0; i < 48; i++) {
        int idx = tid + 256 * i;
        int n = idx >> 6, row = idx & 63;
        float val = rstd_s[row] * Csm[n * CSTR + row] - mrs_s[row] * g_gW[n] + g_bW[n];
        int grp2 = bid * 2 + (row >> 5);
        int h2o = grp2 & 31, d2o = (grp2 >> 5) & 15, bo = grp2 >> 9;
        out[(size_t)bo * NDIM * OSP + (size_t)n * OSP + d2o * (H2 * W2) + h2o * W2 + (row & 31)] = val;
    }
}

// ---------------- launch ----------------
extern "C" void kernel_launch(void* const* d_in, const int* in_sizes, int n_in,
                              void* d_out, int out_size) {
    const float* x     = (const float*)d_in[0];
    const float* gamma = (const float*)d_in[1];
    const float* beta  = (const float*)d_in[2];
    const float* w     = (const float*)d_in[3];
    float* out = (float*)d_out;

    cudaFuncSetAttribute(pm_kernel, cudaFuncAttributeMaxDynamicSharedMemorySize, SMEM_TOTAL);

    zero_vec<<<1, 256>>>();
    prep_vec<<<32, NDIM>>>(gamma, beta, w);
    prep_frag<<<288, 128>>>(gamma, w);
    pm_kernel<<<NCTA, 256, SMEM_TOTAL>>>(x, out);
}